// round 7
// baseline (speedup 1.0000x reference)
#include <cuda_runtime.h>
#include <float.h>
#include <math.h>

// Problem constants (fixed by setup_inputs)
#define NPTS 8192
#define KNN 16
#define GS 64
#define NCELLS (GS * GS)
#define NB 148              // blocks (1 per SM, all co-resident)
#define NT 512              // threads per block
#define NWARPS (NB * (NT / 32))

#define FIXP 16777216.0     // 2^24

// ---------------- scratch (static device globals; no dynamic allocation) ----
__device__ float    g_mx[NPTS], g_my[NPTS];      // ch2m coordinates (SoA)
__device__ unsigned g_benc[4] = {0xFFFFFFFFu, 0u, 0xFFFFFFFFu, 0u}; // enc bbox
__device__ int      g_counts[NCELLS], g_qcounts[NCELLS];
__device__ int      g_start[NCELLS + 1];
__device__ int      g_fill[NCELLS], g_qfill[NCELLS];
__device__ int      g_cellof[NPTS], g_qcell[NPTS];
__device__ float2   g_bxy[NPTS];                 // binned point coords
__device__ int      g_bid[NPTS];                 // binned original point ids
__device__ float2   g_qxy[NPTS];                 // cell-sorted query coords
__device__ int      g_qid[NPTS];                 // cell-sorted original query ids
__device__ int      g_knn[NPTS * KNN];
__device__ long long g_accum;
__device__ volatile int g_bar_cnt;
__device__ volatile int g_bar_gen;

// Order-preserving float <-> unsigned encoding (for atomicMin/Max).
// Static-initialized bbox atomics are idempotent across graph replays:
// identical inputs -> identical extrema -> later replays are no-ops.
__device__ __forceinline__ unsigned encf(float f) {
    unsigned u = __float_as_uint(f);
    return (u & 0x80000000u) ? ~u : (u | 0x80000000u);
}
__device__ __forceinline__ float decf(unsigned u) {
    unsigned v = (u & 0x80000000u) ? (u ^ 0x80000000u) : ~u;
    return __uint_as_float(v);
}

// Grid-wide barrier. Safe: all NB blocks are co-resident (1 per SM).
__device__ __forceinline__ void gbar() {
    __syncthreads();
    if (threadIdx.x == 0) {
        int gen = g_bar_gen;
        __threadfence();
        int old = atomicAdd((int*)&g_bar_cnt, 1);
        if (old == NB - 1) {
            g_bar_cnt = 0;
            __threadfence();
            g_bar_gen = gen + 1;
        } else {
            while (g_bar_gen == gen) __nanosleep(32);
            __threadfence();
        }
    }
    __syncthreads();
}

// Exclusive scan of 4096 ints by one 512-thread block (8 elems/thread).
__device__ __forceinline__ void scan_block0(const int* __restrict__ cnt,
                                            int* __restrict__ start,
                                            int* __restrict__ fill,
                                            bool write_total) {
    __shared__ int wsum[16];
    int t = threadIdx.x, lane = t & 31, w = t >> 5;
    int4 a = ((const int4*)cnt)[2 * t];
    int4 b = ((const int4*)cnt)[2 * t + 1];
    int p1 = a.x, p2 = p1 + a.y, p3 = p2 + a.z, p4 = p3 + a.w;
    int p5 = p4 + b.x, p6 = p5 + b.y, p7 = p6 + b.z, p8 = p7 + b.w;
    int x = p8;
#pragma unroll
    for (int o = 1; o < 32; o <<= 1) {
        int u = __shfl_up_sync(0xFFFFFFFFu, x, o);
        if (lane >= o) x += u;
    }
    if (lane == 31) wsum[w] = x;
    __syncthreads();
    if (w == 0) {
        int y = (lane < 16) ? wsum[lane] : 0;
#pragma unroll
        for (int o = 1; o < 16; o <<= 1) {
            int u = __shfl_up_sync(0xFFFFFFFFu, y, o);
            if (lane >= o) y += u;
        }
        if (lane < 16) wsum[lane] = y;
    }
    __syncthreads();
    int incl = x + (w > 0 ? wsum[w - 1] : 0);
    int ex = incl - p8;
    int4 oa = make_int4(ex, ex + p1, ex + p2, ex + p3);
    int4 ob = make_int4(ex + p4, ex + p5, ex + p6, ex + p7);
    ((int4*)start)[2 * t] = oa;
    ((int4*)start)[2 * t + 1] = ob;
    ((int4*)fill)[2 * t] = oa;
    ((int4*)fill)[2 * t + 1] = ob;
    if (write_total && t == 511) start[NCELLS] = incl;
}

// Map ring-cell index i (0..8r-1) to grid coords for Chebyshev ring r>=1.
__device__ __forceinline__ void ring_cell(int r, int i, int qcx, int qcy,
                                          int& cx, int& cy) {
    int side = 2 * r + 1;
    if (i < side) { cx = qcx - r + i; cy = qcy - r; }
    else if (i < 2 * side) { cx = qcx - r + (i - side); cy = qcy + r; }
    else {
        int j = i - 2 * side;
        cy = qcy - r + 1 + (j >> 1);
        cx = (j & 1) ? qcx + r : qcx - r;
    }
}

// ---------------- the single persistent kernel ------------------------------

__global__ void __launch_bounds__(NT) k_all(const float* __restrict__ ch1,
                                            const float* __restrict__ ch2,
                                            const float* __restrict__ M1,
                                            const float* __restrict__ M2,
                                            float* __restrict__ out) {
    __shared__ float s_red[64];
    __shared__ float s_sum[16];

    int b = blockIdx.x, t = threadIdx.x;
    int lane = t & 31, w = t >> 5;
    int g = b * NT + t;
    int s0 = (int)(((long long)b * NPTS) / NB);
    int e0 = (int)(((long long)(b + 1) * NPTS) / NB);

    // ===== Phase A: zero counts, reset accum, poly map + bbox ===============
    if (g < 1024) ((int4*)g_counts)[g] = make_int4(0, 0, 0, 0);
    else if (g < 2048) ((int4*)g_qcounts)[g - 1024] = make_int4(0, 0, 0, 0);
    if (g == 0) g_accum = 0;

    {
        float m10 = M1[0], m11 = M1[1], m12 = M1[2], m13 = M1[3];
        float m20 = M2[0], m21 = M2[1], m22 = M2[2], m23 = M2[3];
        float mnx = FLT_MAX, mxx = -FLT_MAX, mny = FLT_MAX, mxy = -FLT_MAX;
        for (int i = s0 + t; i < e0; i += NT) {
            float2 c = ((const float2*)ch2)[i];
            float y1 = m10 + m11 * c.y + m12 * c.x + m13 * c.x * c.y;
            float y2 = m20 + m21 * c.y + m22 * c.x + m23 * c.x * c.y;
            g_mx[i] = y1; g_my[i] = y2;
            mnx = fminf(mnx, y1); mxx = fmaxf(mxx, y1);
            mny = fminf(mny, y2); mxy = fmaxf(mxy, y2);
        }
#pragma unroll
        for (int o = 16; o > 0; o >>= 1) {
            mnx = fminf(mnx, __shfl_xor_sync(0xFFFFFFFFu, mnx, o));
            mxx = fmaxf(mxx, __shfl_xor_sync(0xFFFFFFFFu, mxx, o));
            mny = fminf(mny, __shfl_xor_sync(0xFFFFFFFFu, mny, o));
            mxy = fmaxf(mxy, __shfl_xor_sync(0xFFFFFFFFu, mxy, o));
        }
        if (lane == 0) {
            s_red[w] = mnx; s_red[16 + w] = mxx;
            s_red[32 + w] = mny; s_red[48 + w] = mxy;
        }
        __syncthreads();
        if (w == 0) {
            float A = (lane < 16) ? s_red[lane] : FLT_MAX;
            float B = (lane < 16) ? s_red[16 + lane] : -FLT_MAX;
            float C = (lane < 16) ? s_red[32 + lane] : FLT_MAX;
            float D = (lane < 16) ? s_red[48 + lane] : -FLT_MAX;
#pragma unroll
            for (int o = 16; o > 0; o >>= 1) {
                A = fminf(A, __shfl_xor_sync(0xFFFFFFFFu, A, o));
                B = fmaxf(B, __shfl_xor_sync(0xFFFFFFFFu, B, o));
                C = fminf(C, __shfl_xor_sync(0xFFFFFFFFu, C, o));
                D = fmaxf(D, __shfl_xor_sync(0xFFFFFFFFu, D, o));
            }
            if (lane == 0) {
                atomicMin(&g_benc[0], encf(A));
                atomicMax(&g_benc[1], encf(B));
                atomicMin(&g_benc[2], encf(C));
                atomicMax(&g_benc[3], encf(D));
            }
        }
    }
    gbar();

    // ===== Phase B: bin points + queries ====================================
    float minx = decf(g_benc[0]), maxx = decf(g_benc[1]);
    float miny = decf(g_benc[2]), maxy = decf(g_benc[3]);
    float rxr = fmaxf(maxx - minx, 1e-20f);
    float ryr = fmaxf(maxy - miny, 1e-20f);
    float ivx = (float)GS / rxr, ivy = (float)GS / ryr;
    float hx = rxr / (float)GS, hy = ryr / (float)GS;

    for (int i = s0 + t; i < e0; i += NT) {
        int cx = min(GS - 1, max(0, (int)((g_mx[i] - minx) * ivx)));
        int cy = min(GS - 1, max(0, (int)((g_my[i] - miny) * ivy)));
        int c = cy * GS + cx;
        g_cellof[i] = c;
        atomicAdd(&g_counts[c], 1);
        float2 q = ((const float2*)ch1)[i];
        int qcx = min(GS - 1, max(0, (int)((q.x - minx) * ivx)));
        int qcy = min(GS - 1, max(0, (int)((q.y - miny) * ivy)));
        int qc = qcy * GS + qcx;
        g_qcell[i] = qc;
        atomicAdd(&g_qcounts[qc], 1);
    }
    gbar();

    // ===== Phase C: scans (block 0) =========================================
    if (b == 0) {
        scan_block0(g_counts, g_start, g_fill, true);
        __syncthreads();
        scan_block0(g_qcounts, g_qfill, g_qfill, false);
    }
    gbar();

    // ===== Phase D: scatter into cell-sorted order ==========================
    for (int i = s0 + t; i < e0; i += NT) {
        int c = g_cellof[i];
        int p = atomicAdd(&g_fill[c], 1);
        g_bxy[p] = make_float2(g_mx[i], g_my[i]);
        g_bid[p] = i;
        int qc = g_qcell[i];
        int pq = atomicAdd(&g_qfill[qc], 1);
        g_qxy[pq] = ((const float2*)ch1)[i];
        g_qid[pq] = i;
    }
    gbar();

    // ===== Phase E: warp-per-query exact 16-NN ==============================
    {
        int wg = b * (NT / 32) + w;
        for (int q = wg; q < NPTS; q += NWARPS) {
            float2 Q = g_qxy[q];
            float qx = Q.x, qy = Q.y;
            int orig = g_qid[q];
            int qcx = min(GS - 1, max(0, (int)((qx - minx) * ivx)));
            int qcy = min(GS - 1, max(0, (int)((qy - miny) * ivy)));

            float bd[KNN]; int bi[KNN];
#pragma unroll
            for (int s = 0; s < KNN; s++) { bd[s] = FLT_MAX; bi[s] = 0; }

            int cum = 0;
            float D2 = FLT_MAX;
            bool have = false;

            for (int r = 0; r <= 2 * GS; ++r) {
                if (have) {
                    float lb = FLT_MAX;
                    if (qcx - r >= 0) lb = fminf(lb, qx - (minx + (float)(qcx - r + 1) * hx));
                    if (qcx + r < GS) lb = fminf(lb, (minx + (float)(qcx + r) * hx) - qx);
                    if (qcy - r >= 0) lb = fminf(lb, qy - (miny + (float)(qcy - r + 1) * hy));
                    if (qcy + r < GS) lb = fminf(lb, (miny + (float)(qcy + r) * hy) - qy);
                    if (lb == FLT_MAX) break;       // ring fully off-grid
                    lb = fmaxf(lb - 1e-4f, 0.0f);
                    if (lb * lb > D2) break;        // nothing closer can exist
                }
                int ncell = (r == 0) ? 1 : 8 * r;
                int mycnt = 0;
                for (int i = lane; i < ncell; i += 32) {
                    int cx, cy;
                    if (r == 0) { cx = qcx; cy = qcy; }
                    else ring_cell(r, i, qcx, qcy, cx, cy);
                    if (cx < 0 || cx >= GS || cy < 0 || cy >= GS) continue;
                    if (have) {
                        float cx0 = minx + (float)cx * hx;
                        float cy0 = miny + (float)cy * hy;
                        float ddx = fmaxf(0.0f, fmaxf(cx0 - qx, qx - (cx0 + hx)));
                        float ddy = fmaxf(0.0f, fmaxf(cy0 - qy, qy - (cy0 + hy)));
                        ddx = fmaxf(ddx - 1e-4f, 0.0f);
                        ddy = fmaxf(ddy - 1e-4f, 0.0f);
                        if (ddx * ddx + ddy * ddy > D2) continue;
                    }
                    int c = cy * GS + cx;
                    int en = g_start[c + 1];
                    int st = g_start[c];
                    mycnt += en - st;
                    for (int tt = st; tt < en; ++tt) {
                        float2 p = g_bxy[tt];
                        float dx = qx - p.x;
                        float dy = qy - p.y;
                        float d = __fadd_rn(__fmul_rn(dx, dx), __fmul_rn(dy, dy));
                        if (d < bd[KNN - 1]) {
                            bd[KNN - 1] = d;
                            bi[KNN - 1] = g_bid[tt];
#pragma unroll
                            for (int s = KNN - 1; s > 0; --s) {
                                if (bd[s] < bd[s - 1]) {
                                    float td = bd[s]; bd[s] = bd[s - 1]; bd[s - 1] = td;
                                    int ti = bi[s]; bi[s] = bi[s - 1]; bi[s - 1] = ti;
                                }
                            }
                        }
                    }
                }
                if (!have) {
                    cum += __reduce_add_sync(0xFFFFFFFFu, mycnt);
                    if (cum >= KNN) {
                        have = true;
                        // far corner of the scanned square region (r rings)
                        float dxf = fmaxf(qx - (minx + (float)(qcx - r) * hx),
                                          (minx + (float)(qcx + r + 1) * hx) - qx) + 1e-4f;
                        float dyf = fmaxf(qy - (miny + (float)(qcy - r) * hy),
                                          (miny + (float)(qcy + r + 1) * hy) - qy) + 1e-4f;
                        D2 = dxf * dxf + dyf * dyf;
                    }
                }
            }

            // exact sorted top-16 merge across the warp (uint order-isomorphic)
            for (int k = 0; k < KNN; k++) {
                unsigned du = __float_as_uint(bd[0]);
                unsigned m = __reduce_min_sync(0xFFFFFFFFu, du);
                unsigned ball = __ballot_sync(0xFFFFFFFFu, du == m);
                int bl = __ffs(ball) - 1;
                if (lane == bl) {
                    g_knn[orig * KNN + k] = bi[0];
#pragma unroll
                    for (int s = 0; s < KNN - 1; s++) { bd[s] = bd[s + 1]; bi[s] = bi[s + 1]; }
                    bd[KNN - 1] = FLT_MAX;
                }
            }
        }
    }
    gbar();

    // ===== Phase F: scrambled gather + KL log-sum ===========================
    {
        float part = 0.0f;
        for (int n = s0 + t; n < e0; n += NT) {
            float2 qp = ((const float2*)ch1)[n];
            float qx = qp.x, qy = qp.y;
            int qq = n >> 4, col = n & 15;
            const float inv_s4 = 1.0f / 2.25f;  // 1 / sigma2^2, sigma2 = 1.5
            float acc = 0.0f;
#pragma unroll
            for (int k = 0; k < 16; k++) {
                int sel = g_knn[(k * 512 + qq) * KNN + col];
                float dx = qx - g_mx[sel];
                float dy = qy - g_my[sel];
                float D = 0.5f * (__fmul_rn(dx, dx) * inv_s4 + __fmul_rn(dy, dy) * inv_s4);
                acc += expf(-D);
            }
            float expD = acc * (1.0f / (float)NPTS);
            part += (expD != 0.0f) ? logf(expD) : 0.0f;
        }
#pragma unroll
        for (int o = 16; o > 0; o >>= 1)
            part += __shfl_xor_sync(0xFFFFFFFFu, part, o);
        if (lane == 0) s_sum[w] = part;
        __syncthreads();
        if (w == 0) {
            float v = (lane < 16) ? s_sum[lane] : 0.0f;
#pragma unroll
            for (int o = 16; o > 0; o >>= 1)
                v += __shfl_xor_sync(0xFFFFFFFFu, v, o);
            if (lane == 0) {
                long long fv = __double2ll_rn((double)v * FIXP);
                atomicAdd((unsigned long long*)&g_accum, (unsigned long long)fv);
            }
        }
    }
    gbar();

    if (b == 0 && t == 0)
        out[0] = (float)(-((double)g_accum / FIXP));
}

// ---------------- launch ----------------------------------------------------

extern "C" void kernel_launch(void* const* d_in, const int* in_sizes, int n_in,
                              void* d_out, int out_size) {
    (void)in_sizes; (void)n_in; (void)out_size;
    const float* ch1 = (const float*)d_in[0];
    const float* ch2 = (const float*)d_in[1];
    const float* M1  = (const float*)d_in[2];
    const float* M2  = (const float*)d_in[3];
    float* out = (float*)d_out;

    k_all<<<NB, NT>>>(ch1, ch2, M1, M2, out);
}

// round 8
// speedup vs baseline: 1.0166x; 1.0166x over previous
#include <cuda_runtime.h>
#include <float.h>
#include <math.h>

// Problem constants (fixed by setup_inputs)
#define NPTS 8192
#define KNN 16
#define GS 128
#define NCELLS (GS * GS)
#define NB 148              // blocks (1 per SM, all co-resident)
#define NT 512              // threads per block
#define NWARPS (NB * (NT / 32))
#define SMEM_KEYS_BYTES ((NT / 32) * 32 * KNN * 8)   // 64 KB

#define FIXP 16777216.0     // 2^24

// ---------------- scratch (static device globals; no dynamic allocation) ----
__device__ float    g_mx[NPTS], g_my[NPTS];      // ch2m coordinates (SoA)
__device__ unsigned g_benc[4] = {0xFFFFFFFFu, 0u, 0xFFFFFFFFu, 0u}; // enc bbox
__device__ int      g_counts[NCELLS], g_qcounts[NCELLS];
__device__ int      g_start[NCELLS + 1];
__device__ int      g_fill[NCELLS], g_qfill[NCELLS];
__device__ int      g_cellof[NPTS], g_qcell[NPTS];
__device__ float2   g_bxy[NPTS];                 // binned point coords
__device__ int      g_bid[NPTS];                 // binned original point ids
__device__ float2   g_qxy[NPTS];                 // cell-sorted query coords
__device__ int      g_qid[NPTS];                 // cell-sorted original query ids
__device__ int      g_knn[NPTS * KNN];
__device__ long long g_accum;
__device__ volatile int g_bar_cnt;
__device__ volatile int g_bar_gen;

// Order-preserving float <-> unsigned encoding (for atomicMin/Max).
// Static-initialized bbox atomics are idempotent across graph replays.
__device__ __forceinline__ unsigned encf(float f) {
    unsigned u = __float_as_uint(f);
    return (u & 0x80000000u) ? ~u : (u | 0x80000000u);
}
__device__ __forceinline__ float decf(unsigned u) {
    unsigned v = (u & 0x80000000u) ? (u ^ 0x80000000u) : ~u;
    return __uint_as_float(v);
}

// Grid-wide barrier. Safe: all NB blocks are co-resident (1 per SM).
__device__ __forceinline__ void gbar() {
    __syncthreads();
    if (threadIdx.x == 0) {
        int gen = g_bar_gen;
        __threadfence();
        int old = atomicAdd((int*)&g_bar_cnt, 1);
        if (old == NB - 1) {
            g_bar_cnt = 0;
            __threadfence();
            g_bar_gen = gen + 1;
        } else {
            while (g_bar_gen == gen) __nanosleep(32);
            __threadfence();
        }
    }
    __syncthreads();
}

// Exclusive scan of 16384 ints by one 512-thread block (2-pass, 32/thread).
__device__ __forceinline__ void scan16k(const int* __restrict__ cnt,
                                        int* __restrict__ start,
                                        int* __restrict__ fill,
                                        bool write_total) {
    __shared__ int wsum[16];
    int t = threadIdx.x, lane = t & 31, w = t >> 5;
    const int4* c4 = (const int4*)cnt;
    int tot = 0;
#pragma unroll
    for (int j = 0; j < 8; j++) {
        int4 a = c4[t * 8 + j];
        tot += a.x + a.y + a.z + a.w;
    }
    int x = tot;
#pragma unroll
    for (int o = 1; o < 32; o <<= 1) {
        int u = __shfl_up_sync(0xFFFFFFFFu, x, o);
        if (lane >= o) x += u;
    }
    if (lane == 31) wsum[w] = x;
    __syncthreads();
    if (w == 0) {
        int y = (lane < 16) ? wsum[lane] : 0;
#pragma unroll
        for (int o = 1; o < 16; o <<= 1) {
            int u = __shfl_up_sync(0xFFFFFFFFu, y, o);
            if (lane >= o) y += u;
        }
        if (lane < 16) wsum[lane] = y;
    }
    __syncthreads();
    int base = x - tot + (w > 0 ? wsum[w - 1] : 0);
#pragma unroll
    for (int j = 0; j < 8; j++) {
        int4 a = c4[t * 8 + j];
        int4 o;
        o.x = base; o.y = base + a.x; o.z = o.y + a.y; o.w = o.z + a.z;
        base = o.w + a.w;
        ((int4*)start)[t * 8 + j] = o;
        ((int4*)fill)[t * 8 + j] = o;
    }
    if (write_total && t == 511) start[NCELLS] = base;
}

// Count points in the clamped square of Chebyshev radius r around (qcx,qcy).
// Warp-collective; rows are contiguous CSR spans.
__device__ __forceinline__ int count_square(int qcx, int qcy, int r, int lane) {
    int xl = max(0, qcx - r), xr = min(GS - 1, qcx + r);
    int yl = max(0, qcy - r), yh = min(GS - 1, qcy + r);
    int c = 0;
    for (int y = yl + lane; y <= yh; y += 32)
        c += g_start[y * GS + xr + 1] - g_start[y * GS + xl];
    return __reduce_add_sync(0xFFFFFFFFu, c);
}

// ---------------- the single persistent kernel ------------------------------

__global__ void __launch_bounds__(NT) k_all(const float* __restrict__ ch1,
                                            const float* __restrict__ ch2,
                                            const float* __restrict__ M1,
                                            const float* __restrict__ M2,
                                            float* __restrict__ out) {
    extern __shared__ unsigned long long s_keys[];   // [warps][32][16]
    __shared__ float s_red[64];
    __shared__ float s_sum[16];

    int b = blockIdx.x, t = threadIdx.x;
    int lane = t & 31, w = t >> 5;
    int g = b * NT + t;
    int s0 = (int)(((long long)b * NPTS) / NB);
    int e0 = (int)(((long long)(b + 1) * NPTS) / NB);

    // ===== Phase A: zero counts, reset accum, poly map + bbox ===============
    if (g < 4096) ((int4*)g_counts)[g] = make_int4(0, 0, 0, 0);
    else if (g < 8192) ((int4*)g_qcounts)[g - 4096] = make_int4(0, 0, 0, 0);
    if (g == 0) g_accum = 0;

    {
        float m10 = M1[0], m11 = M1[1], m12 = M1[2], m13 = M1[3];
        float m20 = M2[0], m21 = M2[1], m22 = M2[2], m23 = M2[3];
        float mnx = FLT_MAX, mxx = -FLT_MAX, mny = FLT_MAX, mxy = -FLT_MAX;
        for (int i = s0 + t; i < e0; i += NT) {
            float2 c = ((const float2*)ch2)[i];
            float y1 = m10 + m11 * c.y + m12 * c.x + m13 * c.x * c.y;
            float y2 = m20 + m21 * c.y + m22 * c.x + m23 * c.x * c.y;
            g_mx[i] = y1; g_my[i] = y2;
            mnx = fminf(mnx, y1); mxx = fmaxf(mxx, y1);
            mny = fminf(mny, y2); mxy = fmaxf(mxy, y2);
        }
#pragma unroll
        for (int o = 16; o > 0; o >>= 1) {
            mnx = fminf(mnx, __shfl_xor_sync(0xFFFFFFFFu, mnx, o));
            mxx = fmaxf(mxx, __shfl_xor_sync(0xFFFFFFFFu, mxx, o));
            mny = fminf(mny, __shfl_xor_sync(0xFFFFFFFFu, mny, o));
            mxy = fmaxf(mxy, __shfl_xor_sync(0xFFFFFFFFu, mxy, o));
        }
        if (lane == 0) {
            s_red[w] = mnx; s_red[16 + w] = mxx;
            s_red[32 + w] = mny; s_red[48 + w] = mxy;
        }
        __syncthreads();
        if (w == 0) {
            float A = (lane < 16) ? s_red[lane] : FLT_MAX;
            float B = (lane < 16) ? s_red[16 + lane] : -FLT_MAX;
            float C = (lane < 16) ? s_red[32 + lane] : FLT_MAX;
            float D = (lane < 16) ? s_red[48 + lane] : -FLT_MAX;
#pragma unroll
            for (int o = 16; o > 0; o >>= 1) {
                A = fminf(A, __shfl_xor_sync(0xFFFFFFFFu, A, o));
                B = fmaxf(B, __shfl_xor_sync(0xFFFFFFFFu, B, o));
                C = fminf(C, __shfl_xor_sync(0xFFFFFFFFu, C, o));
                D = fmaxf(D, __shfl_xor_sync(0xFFFFFFFFu, D, o));
            }
            if (lane == 0) {
                atomicMin(&g_benc[0], encf(A));
                atomicMax(&g_benc[1], encf(B));
                atomicMin(&g_benc[2], encf(C));
                atomicMax(&g_benc[3], encf(D));
            }
        }
    }
    gbar();

    // ===== Phase B: bin points + queries ====================================
    float minx = decf(g_benc[0]), maxx = decf(g_benc[1]);
    float miny = decf(g_benc[2]), maxy = decf(g_benc[3]);
    float rxr = fmaxf(maxx - minx, 1e-20f);
    float ryr = fmaxf(maxy - miny, 1e-20f);
    float ivx = (float)GS / rxr, ivy = (float)GS / ryr;
    float hx = rxr / (float)GS, hy = ryr / (float)GS;

    for (int i = s0 + t; i < e0; i += NT) {
        int cx = min(GS - 1, max(0, (int)((g_mx[i] - minx) * ivx)));
        int cy = min(GS - 1, max(0, (int)((g_my[i] - miny) * ivy)));
        int c = cy * GS + cx;
        g_cellof[i] = c;
        atomicAdd(&g_counts[c], 1);
        float2 q = ((const float2*)ch1)[i];
        int qcx = min(GS - 1, max(0, (int)((q.x - minx) * ivx)));
        int qcy = min(GS - 1, max(0, (int)((q.y - miny) * ivy)));
        int qc = qcy * GS + qcx;
        g_qcell[i] = qc;
        atomicAdd(&g_qcounts[qc], 1);
    }
    gbar();

    // ===== Phase C: scans (block 0) =========================================
    if (b == 0) {
        scan16k(g_counts, g_start, g_fill, true);
        __syncthreads();
        scan16k(g_qcounts, g_qfill, g_qfill, false);
    }
    gbar();

    // ===== Phase D: scatter into cell-sorted order ==========================
    for (int i = s0 + t; i < e0; i += NT) {
        int c = g_cellof[i];
        int p = atomicAdd(&g_fill[c], 1);
        g_bxy[p] = make_float2(g_mx[i], g_my[i]);
        g_bid[p] = i;
        int qc = g_qcell[i];
        int pq = atomicAdd(&g_qfill[qc], 1);
        g_qxy[pq] = ((const float2*)ch1)[i];
        g_qid[pq] = i;
    }
    gbar();

    // ===== Phase E: warp-per-query exact 16-NN (row-span D-box scan) ========
    {
        int wg = b * (NT / 32) + w;
        int q0 = (int)(((long long)wg * NPTS) / NWARPS);
        int q1 = (int)(((long long)(wg + 1) * NPTS) / NWARPS);
        unsigned long long kbase = (unsigned long long)(w * 32 + lane) * KNN;

        for (int q = q0; q < q1; ++q) {
            float2 Q = g_qxy[q];
            float qx = Q.x, qy = Q.y;
            int orig = g_qid[q];
            int qcx = min(GS - 1, max(0, (int)((qx - minx) * ivx)));
            int qcy = min(GS - 1, max(0, (int)((qy - miny) * ivy)));

            // ---- count-expand squares until >= KNN, then binary-refine r0.
            int lo = 0, r = 1;
            int cnt = count_square(qcx, qcy, r, lane);
            while (cnt < KNN && r < GS) {
                lo = r;
                r = min(GS, r + 1 + (r >> 1));
                cnt = count_square(qcx, qcy, r, lane);
            }
            while (r - lo > 1) {
                int mid = (r + lo) >> 1;
                if (count_square(qcx, qcy, mid, lane) >= KNN) r = mid;
                else lo = mid;
            }
            int r0 = r;

            // ---- D2 = far-corner bound of the counted square (conservative).
            float dxf = fmaxf(qx - (minx + (float)(qcx - r0) * hx),
                              (minx + (float)(qcx + r0 + 1) * hx) - qx) + 1e-4f;
            float dyf = fmaxf(qy - (miny + (float)(qcy - r0) * hy),
                              (miny + (float)(qcy + r0 + 1) * hy) - qy) + 1e-4f;
            float D2 = dxf * dxf + dyf * dyf;
            float Dr = sqrtf(D2);

            // ---- D-box in cells (+1 margin for binning fp rounding).
            int bx0 = max(0, (int)floorf((qx - Dr - minx) * ivx) - 1);
            int bx1 = min(GS - 1, (int)floorf((qx + Dr - minx) * ivx) + 1);
            int by0 = max(0, (int)floorf((qy - Dr - miny) * ivy) - 1);
            int by1 = min(GS - 1, (int)floorf((qy + Dr - miny) * ivy) + 1);

            // ---- scan: rows are contiguous CSR spans, lane-strided points.
            float bd[KNN]; int bi[KNN];
#pragma unroll
            for (int s = 0; s < KNN; s++) { bd[s] = FLT_MAX; bi[s] = 0x7FFFFFFF; }

            int nrows = by1 - by0 + 1;
            for (int chv = 0; chv < nrows; chv += 32) {
                int y = by0 + chv + lane;
                int mrs = 0, mre = 0;
                if (y <= by1) {
                    mrs = g_start[y * GS + bx0];
                    mre = g_start[y * GS + bx1 + 1];
                }
                int lim = min(32, nrows - chv);
                for (int j = 0; j < lim; ++j) {
                    int rs = __shfl_sync(0xFFFFFFFFu, mrs, j);
                    int re = __shfl_sync(0xFFFFFFFFu, mre, j);
                    for (int tt = rs + lane; tt < re; tt += 32) {
                        float2 p = g_bxy[tt];
                        float dx = qx - p.x;
                        float dy = qy - p.y;
                        float d = __fadd_rn(__fmul_rn(dx, dx), __fmul_rn(dy, dy));
                        int id = g_bid[tt];
                        if (d < bd[KNN - 1] ||
                            (d == bd[KNN - 1] && id < bi[KNN - 1])) {
                            bd[KNN - 1] = d;
                            bi[KNN - 1] = id;
#pragma unroll
                            for (int s = KNN - 1; s > 0; --s) {
                                bool sw = (bd[s] < bd[s - 1]) ||
                                          (bd[s] == bd[s - 1] && bi[s] < bi[s - 1]);
                                if (sw) {
                                    float td = bd[s]; bd[s] = bd[s - 1]; bd[s - 1] = td;
                                    int ti = bi[s]; bi[s] = bi[s - 1]; bi[s - 1] = ti;
                                }
                            }
                        }
                    }
                }
            }

            // ---- exact sorted warp merge via smem keys (dist_bits<<32 | id).
#pragma unroll
            for (int s = 0; s < KNN; s++)
                s_keys[kbase + s] =
                    ((unsigned long long)__float_as_uint(bd[s]) << 32) | (unsigned)bi[s];
            int head = 0;
            unsigned long long cur = s_keys[kbase];
#pragma unroll 1
            for (int k = 0; k < KNN; k++) {
                unsigned hi = (unsigned)(cur >> 32);
                unsigned m = __reduce_min_sync(0xFFFFFFFFu, hi);
                unsigned lov = (hi == m) ? (unsigned)cur : 0xFFFFFFFFu;
                unsigned ml = __reduce_min_sync(0xFFFFFFFFu, lov);
                if (lane == 0) g_knn[orig * KNN + k] = (int)ml;
                if (hi == m && (unsigned)cur == ml) {
                    head++;
                    cur = (head < KNN) ? s_keys[kbase + head] : 0xFFFFFFFFFFFFFFFFull;
                }
            }
        }
    }
    gbar();

    // ===== Phase F: scrambled gather + KL log-sum ===========================
    {
        float part = 0.0f;
        for (int n = s0 + t; n < e0; n += NT) {
            float2 qp = ((const float2*)ch1)[n];
            float qx = qp.x, qy = qp.y;
            int qq = n >> 4, col = n & 15;
            const float inv_s4 = 1.0f / 2.25f;  // 1 / sigma2^2, sigma2 = 1.5
            float acc = 0.0f;
#pragma unroll
            for (int k = 0; k < 16; k++) {
                int sel = g_knn[(k * 512 + qq) * KNN + col];
                float dx = qx - g_mx[sel];
                float dy = qy - g_my[sel];
                float D = 0.5f * (__fmul_rn(dx, dx) * inv_s4 + __fmul_rn(dy, dy) * inv_s4);
                acc += expf(-D);
            }
            float expD = acc * (1.0f / (float)NPTS);
            part += (expD != 0.0f) ? logf(expD) : 0.0f;
        }
#pragma unroll
        for (int o = 16; o > 0; o >>= 1)
            part += __shfl_xor_sync(0xFFFFFFFFu, part, o);
        if (lane == 0) s_sum[w] = part;
        __syncthreads();
        if (w == 0) {
            float v = (lane < 16) ? s_sum[lane] : 0.0f;
#pragma unroll
            for (int o = 16; o > 0; o >>= 1)
                v += __shfl_xor_sync(0xFFFFFFFFu, v, o);
            if (lane == 0) {
                long long fv = __double2ll_rn((double)v * FIXP);
                atomicAdd((unsigned long long*)&g_accum, (unsigned long long)fv);
            }
        }
    }
    gbar();

    if (b == 0 && t == 0)
        out[0] = (float)(-((double)g_accum / FIXP));
}

// ---------------- launch ----------------------------------------------------

extern "C" void kernel_launch(void* const* d_in, const int* in_sizes, int n_in,
                              void* d_out, int out_size) {
    (void)in_sizes; (void)n_in; (void)out_size;
    const float* ch1 = (const float*)d_in[0];
    const float* ch2 = (const float*)d_in[1];
    const float* M1  = (const float*)d_in[2];
    const float* M2  = (const float*)d_in[3];
    float* out = (float*)d_out;

    cudaFuncSetAttribute(k_all, cudaFuncAttributeMaxDynamicSharedMemorySize,
                         SMEM_KEYS_BYTES);
    k_all<<<NB, NT, SMEM_KEYS_BYTES>>>(ch1, ch2, M1, M2, out);
}

// round 9
// speedup vs baseline: 1.6123x; 1.5859x over previous
#include <cuda_runtime.h>
#include <float.h>
#include <math.h>

// Problem constants (fixed by setup_inputs)
#define NPTS 8192
#define KNN 16
#define GS 192
#define NCELLS (GS * GS)          // 36864
#define NB 148                    // blocks (1 per SM, all co-resident)
#define NT 512                    // threads per block
#define NWPB (NT / 32)
#define NWARPS (NB * NWPB)
#define SMEM_KEYS_BYTES (NWPB * 32 * KNN * 8)   // 64 KB

#define FIXP 16777216.0           // 2^24

typedef unsigned long long u64;

// ---------------- scratch (static device globals; no dynamic allocation) ----
__device__ float    g_mx[NPTS], g_my[NPTS];
__device__ unsigned g_benc[4] = {0xFFFFFFFFu, 0u, 0xFFFFFFFFu, 0u};
__device__ int      g_counts[NCELLS], g_qcounts[NCELLS];
__device__ int      g_start[NCELLS + 1];
__device__ int      g_fill[NCELLS], g_qfill[NCELLS];
__device__ int      g_cellof[NPTS], g_qcell[NPTS];
__device__ float4   g_bpt[NPTS];                 // x, y, id_bits, 0
__device__ float2   g_qxy[NPTS];
__device__ int      g_qid[NPTS];
__device__ int      g_r0[NCELLS];                // per-query-cell square radius
__device__ int      g_knn[NPTS * KNN];
__device__ long long g_accum;
__device__ int      g_qnext;
__device__ volatile int g_bar_cnt;
__device__ volatile int g_bar_gen;

__device__ __forceinline__ unsigned encf(float f) {
    unsigned u = __float_as_uint(f);
    return (u & 0x80000000u) ? ~u : (u | 0x80000000u);
}
__device__ __forceinline__ float decf(unsigned u) {
    unsigned v = (u & 0x80000000u) ? (u ^ 0x80000000u) : ~u;
    return __uint_as_float(v);
}

// Grid-wide barrier. Safe: all NB blocks are co-resident (1 per SM).
__device__ __forceinline__ void gbar() {
    __syncthreads();
    if (threadIdx.x == 0) {
        int gen = g_bar_gen;
        __threadfence();
        int old = atomicAdd((int*)&g_bar_cnt, 1);
        if (old == NB - 1) {
            g_bar_cnt = 0;
            __threadfence();
            g_bar_gen = gen + 1;
        } else {
            while (g_bar_gen == gen) __nanosleep(32);
            __threadfence();
        }
    }
    __syncthreads();
}

// Exclusive scan of NCELLS ints by one 512-thread block (2-pass, 72/thread).
__device__ __forceinline__ void scanN(const int* __restrict__ cnt,
                                      int* __restrict__ outp,
                                      int* __restrict__ outp2,
                                      bool write_total) {
    __shared__ int wsum[16];
    int t = threadIdx.x, lane = t & 31, w = t >> 5;
    const int4* c4 = (const int4*)cnt;
    const int PT = NCELLS / NT / 4;      // int4s per thread = 18
    int tot = 0;
#pragma unroll 6
    for (int j = 0; j < PT; j++) {
        int4 a = c4[t * PT + j];
        tot += a.x + a.y + a.z + a.w;
    }
    int x = tot;
#pragma unroll
    for (int o = 1; o < 32; o <<= 1) {
        int u = __shfl_up_sync(0xFFFFFFFFu, x, o);
        if (lane >= o) x += u;
    }
    if (lane == 31) wsum[w] = x;
    __syncthreads();
    if (w == 0) {
        int y = (lane < 16) ? wsum[lane] : 0;
#pragma unroll
        for (int o = 1; o < 16; o <<= 1) {
            int u = __shfl_up_sync(0xFFFFFFFFu, y, o);
            if (lane >= o) y += u;
        }
        if (lane < 16) wsum[lane] = y;
    }
    __syncthreads();
    int run = x - tot + (w > 0 ? wsum[w - 1] : 0);
#pragma unroll 6
    for (int j = 0; j < PT; j++) {
        int4 a = c4[t * PT + j];
        int4 o;
        o.x = run; o.y = run + a.x; o.z = o.y + a.y; o.w = o.z + a.z;
        run = o.w + a.w;
        ((int4*)outp)[t * PT + j] = o;
        ((int4*)outp2)[t * PT + j] = o;
    }
    if (write_total && t == NT - 1) outp[NCELLS] = run;
}

// Warp-collective count of points in clamped square radius r around (cx,cy).
__device__ __forceinline__ int count_square(int qcx, int qcy, int r, int lane) {
    int xl = max(0, qcx - r), xr = min(GS - 1, qcx + r);
    int yl = max(0, qcy - r), yh = min(GS - 1, qcy + r);
    int c = 0;
    for (int y = yl + lane; y <= yh; y += 32)
        c += g_start[y * GS + xr + 1] - g_start[y * GS + xl];
    return __reduce_add_sync(0xFFFFFFFFu, c);
}

// ---------------- the single persistent kernel ------------------------------

__global__ void __launch_bounds__(NT) k_all(const float* __restrict__ ch1,
                                            const float* __restrict__ ch2,
                                            const float* __restrict__ M1,
                                            const float* __restrict__ M2,
                                            float* __restrict__ out) {
    extern __shared__ u64 s_keys[];     // interleaved: [(w*KNN + s)*32 + lane]
    __shared__ float s_red[64];
    __shared__ float s_sum[16];

    int b = blockIdx.x, t = threadIdx.x;
    int lane = t & 31, w = t >> 5;
    int g = b * NT + t;
    int s0 = (int)(((long long)b * NPTS) / NB);
    int e0 = (int)(((long long)(b + 1) * NPTS) / NB);

    // ===== Phase A: zero counts, reset scalars, poly map + bbox =============
    {
        const int NQ4 = NCELLS / 4;      // 9216
        if (g < NQ4) ((int4*)g_counts)[g] = make_int4(0, 0, 0, 0);
        else if (g < 2 * NQ4) ((int4*)g_qcounts)[g - NQ4] = make_int4(0, 0, 0, 0);
        if (g == 0) { g_accum = 0; g_qnext = 0; }

        float m10 = M1[0], m11 = M1[1], m12 = M1[2], m13 = M1[3];
        float m20 = M2[0], m21 = M2[1], m22 = M2[2], m23 = M2[3];
        float mnx = FLT_MAX, mxx = -FLT_MAX, mny = FLT_MAX, mxy = -FLT_MAX;
        for (int i = s0 + t; i < e0; i += NT) {
            float2 c = ((const float2*)ch2)[i];
            float y1 = m10 + m11 * c.y + m12 * c.x + m13 * c.x * c.y;
            float y2 = m20 + m21 * c.y + m22 * c.x + m23 * c.x * c.y;
            g_mx[i] = y1; g_my[i] = y2;
            mnx = fminf(mnx, y1); mxx = fmaxf(mxx, y1);
            mny = fminf(mny, y2); mxy = fmaxf(mxy, y2);
        }
#pragma unroll
        for (int o = 16; o > 0; o >>= 1) {
            mnx = fminf(mnx, __shfl_xor_sync(0xFFFFFFFFu, mnx, o));
            mxx = fmaxf(mxx, __shfl_xor_sync(0xFFFFFFFFu, mxx, o));
            mny = fminf(mny, __shfl_xor_sync(0xFFFFFFFFu, mny, o));
            mxy = fmaxf(mxy, __shfl_xor_sync(0xFFFFFFFFu, mxy, o));
        }
        if (lane == 0) {
            s_red[w] = mnx; s_red[16 + w] = mxx;
            s_red[32 + w] = mny; s_red[48 + w] = mxy;
        }
        __syncthreads();
        if (w == 0) {
            float A = (lane < 16) ? s_red[lane] : FLT_MAX;
            float B = (lane < 16) ? s_red[16 + lane] : -FLT_MAX;
            float C = (lane < 16) ? s_red[32 + lane] : FLT_MAX;
            float D = (lane < 16) ? s_red[48 + lane] : -FLT_MAX;
#pragma unroll
            for (int o = 16; o > 0; o >>= 1) {
                A = fminf(A, __shfl_xor_sync(0xFFFFFFFFu, A, o));
                B = fmaxf(B, __shfl_xor_sync(0xFFFFFFFFu, B, o));
                C = fminf(C, __shfl_xor_sync(0xFFFFFFFFu, C, o));
                D = fmaxf(D, __shfl_xor_sync(0xFFFFFFFFu, D, o));
            }
            if (lane == 0) {
                atomicMin(&g_benc[0], encf(A));
                atomicMax(&g_benc[1], encf(B));
                atomicMin(&g_benc[2], encf(C));
                atomicMax(&g_benc[3], encf(D));
            }
        }
    }
    gbar();

    // ===== Phase B: bin points + queries ====================================
    float minx = decf(g_benc[0]), maxx = decf(g_benc[1]);
    float miny = decf(g_benc[2]), maxy = decf(g_benc[3]);
    float rxr = fmaxf(maxx - minx, 1e-20f);
    float ryr = fmaxf(maxy - miny, 1e-20f);
    float ivx = (float)GS / rxr, ivy = (float)GS / ryr;
    float hx = rxr / (float)GS, hy = ryr / (float)GS;

    for (int i = s0 + t; i < e0; i += NT) {
        int cx = min(GS - 1, max(0, (int)((g_mx[i] - minx) * ivx)));
        int cy = min(GS - 1, max(0, (int)((g_my[i] - miny) * ivy)));
        int c = cy * GS + cx;
        g_cellof[i] = c;
        atomicAdd(&g_counts[c], 1);
        float2 q = ((const float2*)ch1)[i];
        int qcx = min(GS - 1, max(0, (int)((q.x - minx) * ivx)));
        int qcy = min(GS - 1, max(0, (int)((q.y - miny) * ivy)));
        int qc = qcy * GS + qcx;
        g_qcell[i] = qc;
        atomicAdd(&g_qcounts[qc], 1);
    }
    gbar();

    // ===== Phase C: scans (blocks 0 and 1 in parallel) ======================
    if (b == 0) scanN(g_counts, g_start, g_fill, true);
    else if (b == 1) scanN(g_qcounts, g_qfill, g_qfill, false);
    gbar();

    // ===== Phase D: scatter + per-cell r0 precompute ========================
    for (int i = s0 + t; i < e0; i += NT) {
        int c = g_cellof[i];
        int p = atomicAdd(&g_fill[c], 1);
        g_bpt[p] = make_float4(g_mx[i], g_my[i], __int_as_float(i), 0.0f);
        int qc = g_qcell[i];
        int pq = atomicAdd(&g_qfill[qc], 1);
        g_qxy[pq] = ((const float2*)ch1)[i];
        g_qid[pq] = i;
    }
    // E0: exact minimal r0 per occupied query cell, lanes 0-15 test r=1..16
    {
        int wg = b * NWPB + w;
        for (int cell = wg; cell < NCELLS; cell += NWARPS) {
            if (g_qcounts[cell] == 0) continue;
            int qcx = cell % GS, qcy = cell / GS;
            int cnt = 0;
            if (lane < 16) {
                int rr = lane + 1;
                int xl = max(0, qcx - rr), xr = min(GS - 1, qcx + rr);
                int yl = max(0, qcy - rr), yh = min(GS - 1, qcy + rr);
                for (int y = yl; y <= yh; ++y)
                    cnt += g_start[y * GS + xr + 1] - g_start[y * GS + xl];
            }
            unsigned ball = __ballot_sync(0xFFFFFFFFu, (lane < 16) && (cnt >= KNN));
            int r0v;
            if (ball) {
                r0v = __ffs(ball);               // lane idx + 1 == radius
            } else {                             // sparse edge cell: expand
                int lo = 16, hi = 24;
                int c2 = count_square(qcx, qcy, hi, lane);
                while (c2 < KNN && hi < GS) {
                    lo = hi; hi = min(GS, hi + (hi >> 1));
                    c2 = count_square(qcx, qcy, hi, lane);
                }
                while (hi - lo > 1) {
                    int mid = (lo + hi) >> 1;
                    if (count_square(qcx, qcy, mid, lane) >= KNN) hi = mid;
                    else lo = mid;
                }
                r0v = hi;
            }
            if (lane == 0) g_r0[cell] = r0v;
        }
    }
    gbar();

    // ===== Phase E: dynamic warp-per-query exact 16-NN ======================
    {
        for (;;) {
            int q;
            if (lane == 0) q = atomicAdd(&g_qnext, 1);
            q = __shfl_sync(0xFFFFFFFFu, q, 0);
            if (q >= NPTS) break;

            float2 Q = g_qxy[q];
            float qx = Q.x, qy = Q.y;
            int orig = g_qid[q];
            int qcx = min(GS - 1, max(0, (int)((qx - minx) * ivx)));
            int qcy = min(GS - 1, max(0, (int)((qy - miny) * ivy)));
            int r0 = g_r0[qcy * GS + qcx];

            // D2 = far-corner bound of the r0-square around the cell.
            float dxf = fmaxf(qx - (minx + (float)(qcx - r0) * hx),
                              (minx + (float)(qcx + r0 + 1) * hx) - qx) + 1e-4f;
            float dyf = fmaxf(qy - (miny + (float)(qcy - r0) * hy),
                              (miny + (float)(qcy + r0 + 1) * hy) - qy) + 1e-4f;
            float D2 = dxf * dxf + dyf * dyf;
            float Dr = sqrtf(D2);

            int bx0 = max(0, (int)floorf((qx - Dr - minx) * ivx) - 1);
            int bx1 = min(GS - 1, (int)floorf((qx + Dr - minx) * ivx) + 1);
            int by0 = max(0, (int)floorf((qy - Dr - miny) * ivy) - 1);
            int by1 = min(GS - 1, (int)floorf((qy + Dr - miny) * ivy) + 1);

            u64 keys[KNN];
#pragma unroll
            for (int s = 0; s < KNN; s++) keys[s] = 0xFFFFFFFFFFFFFFFFull;

            for (int ybase = by0; ybase <= by1; ybase += 32) {
                int y = ybase + lane;
                int rs = 0, len = 0;
                if (y <= by1) {
                    rs = g_start[y * GS + bx0];
                    len = g_start[y * GS + bx1 + 1] - rs;
                }
                int pre = len;
#pragma unroll
                for (int o = 1; o < 32; o <<= 1) {
                    int u = __shfl_up_sync(0xFFFFFFFFu, pre, o);
                    if (lane >= o) pre += u;
                }
                int T = __shfl_sync(0xFFFFFFFFu, pre, 31);
                int excl = pre - len;

                for (int base = 0; base < T; base += 32) {
                    int idx = base + lane;
                    bool act = idx < T;
                    // find row j = max{j : excl_j <= idx} via shfl binary search
                    int jlo = 0;
#pragma unroll
                    for (int s = 16; s > 0; s >>= 1) {
                        int jm = jlo + s;
                        int ev = __shfl_sync(0xFFFFFFFFu, excl, min(jm, 31));
                        if (jm <= 31 && ev <= idx) jlo = jm;
                    }
                    int rrs = __shfl_sync(0xFFFFFFFFu, rs, jlo);
                    int rex = __shfl_sync(0xFFFFFFFFu, excl, jlo);
                    if (act) {
                        int tt = rrs + (idx - rex);
                        float4 p = g_bpt[tt];
                        float dx = qx - p.x;
                        float dy = qy - p.y;
                        float d = __fadd_rn(__fmul_rn(dx, dx), __fmul_rn(dy, dy));
                        if (d <= D2) {
                            u64 key = ((u64)__float_as_uint(d) << 32) |
                                      (unsigned)__float_as_int(p.z);
                            if (key < keys[KNN - 1]) {
                                keys[KNN - 1] = key;
#pragma unroll
                                for (int s = KNN - 1; s > 0; --s) {
                                    if (keys[s] < keys[s - 1]) {
                                        u64 tk = keys[s];
                                        keys[s] = keys[s - 1];
                                        keys[s - 1] = tk;
                                    }
                                }
                            }
                        }
                    }
                }
            }

            // exact sorted warp merge: interleaved smem + 2xREDUX per round
#pragma unroll
            for (int s = 0; s < KNN; s++)
                s_keys[(w * KNN + s) * 32 + lane] = keys[s];
            int head = 0;
            u64 cur = keys[0];
#pragma unroll 1
            for (int k = 0; k < KNN; k++) {
                unsigned hi = (unsigned)(cur >> 32);
                unsigned m = __reduce_min_sync(0xFFFFFFFFu, hi);
                unsigned lov = (hi == m) ? (unsigned)cur : 0xFFFFFFFFu;
                unsigned ml = __reduce_min_sync(0xFFFFFFFFu, lov);
                if (lane == 0) g_knn[orig * KNN + k] = (int)ml;
                if (hi == m && (unsigned)cur == ml) {
                    head++;
                    cur = (head < KNN) ? s_keys[(w * KNN + head) * 32 + lane]
                                       : 0xFFFFFFFFFFFFFFFFull;
                }
            }
        }
    }
    gbar();

    // ===== Phase F: scrambled gather + KL log-sum ===========================
    {
        float part = 0.0f;
        for (int n = s0 + t; n < e0; n += NT) {
            float2 qp = ((const float2*)ch1)[n];
            float qx = qp.x, qy = qp.y;
            int qq = n >> 4, col = n & 15;
            const float inv_s4 = 1.0f / 2.25f;  // 1 / sigma2^2, sigma2 = 1.5
            float acc = 0.0f;
#pragma unroll
            for (int k = 0; k < 16; k++) {
                int sel = g_knn[(k * 512 + qq) * KNN + col];
                float dx = qx - g_mx[sel];
                float dy = qy - g_my[sel];
                float D = 0.5f * (__fmul_rn(dx, dx) * inv_s4 + __fmul_rn(dy, dy) * inv_s4);
                acc += expf(-D);
            }
            float expD = acc * (1.0f / (float)NPTS);
            part += (expD != 0.0f) ? logf(expD) : 0.0f;
        }
#pragma unroll
        for (int o = 16; o > 0; o >>= 1)
            part += __shfl_xor_sync(0xFFFFFFFFu, part, o);
        if (lane == 0) s_sum[w] = part;
        __syncthreads();
        if (w == 0) {
            float v = (lane < 16) ? s_sum[lane] : 0.0f;
#pragma unroll
            for (int o = 16; o > 0; o >>= 1)
                v += __shfl_xor_sync(0xFFFFFFFFu, v, o);
            if (lane == 0) {
                long long fv = __double2ll_rn((double)v * FIXP);
                atomicAdd((unsigned long long*)&g_accum, (unsigned long long)fv);
            }
        }
    }
    gbar();

    if (b == 0 && t == 0)
        out[0] = (float)(-((double)g_accum / FIXP));
}

// ---------------- launch ----------------------------------------------------

extern "C" void kernel_launch(void* const* d_in, const int* in_sizes, int n_in,
                              void* d_out, int out_size) {
    (void)in_sizes; (void)n_in; (void)out_size;
    const float* ch1 = (const float*)d_in[0];
    const float* ch2 = (const float*)d_in[1];
    const float* M1  = (const float*)d_in[2];
    const float* M2  = (const float*)d_in[3];
    float* out = (float*)d_out;

    cudaFuncSetAttribute(k_all, cudaFuncAttributeMaxDynamicSharedMemorySize,
                         SMEM_KEYS_BYTES);
    k_all<<<NB, NT, SMEM_KEYS_BYTES>>>(ch1, ch2, M1, M2, out);
}

// round 10
// speedup vs baseline: 1.9304x; 1.1973x over previous
#include <cuda_runtime.h>
#include <float.h>
#include <math.h>

// Problem constants (fixed by setup_inputs)
#define NPTS 8192
#define KNN 16
#define GS 192
#define NCELLS (GS * GS)          // 36864
#define NB 148                    // blocks (1 per SM, all co-resident)
#define NT 1024                   // threads per block (32 warps/SM)
#define NWPB (NT / 32)
#define NWARPS (NB * NWPB)
#define SMEM_KEYS_BYTES (NWPB * 32 * KNN * 8)   // 128 KB

#define FIXP 16777216.0           // 2^24

typedef unsigned long long u64;

// ---------------- scratch (static device globals; no dynamic allocation) ----
__device__ float    g_mx[NPTS], g_my[NPTS];
__device__ unsigned g_benc[4] = {0xFFFFFFFFu, 0u, 0xFFFFFFFFu, 0u};
__device__ int      g_counts[NCELLS], g_qcounts[NCELLS];
__device__ int      g_start[NCELLS + 1];
__device__ int      g_fill[NCELLS], g_qfill[NCELLS];
__device__ int      g_cellof[NPTS], g_qcell[NPTS];
__device__ float4   g_bpt[NPTS];                 // x, y, id_bits, 0
__device__ float2   g_qxy[NPTS];
__device__ int      g_qid[NPTS];
__device__ int      g_r0[NCELLS];                // per-query-cell square radius
__device__ int      g_knn[NPTS * KNN];
__device__ long long g_accum;
__device__ int      g_qnext;
__device__ volatile int g_bar_cnt;
__device__ volatile int g_bar_gen;

__device__ __forceinline__ unsigned encf(float f) {
    unsigned u = __float_as_uint(f);
    return (u & 0x80000000u) ? ~u : (u | 0x80000000u);
}
__device__ __forceinline__ float decf(unsigned u) {
    unsigned v = (u & 0x80000000u) ? (u ^ 0x80000000u) : ~u;
    return __uint_as_float(v);
}

// Grid-wide barrier. Safe: all NB blocks are co-resident (1 per SM).
__device__ __forceinline__ void gbar() {
    __syncthreads();
    if (threadIdx.x == 0) {
        int gen = g_bar_gen;
        __threadfence();
        int old = atomicAdd((int*)&g_bar_cnt, 1);
        if (old == NB - 1) {
            g_bar_cnt = 0;
            __threadfence();
            g_bar_gen = gen + 1;
        } else {
            while (g_bar_gen == gen) __nanosleep(32);
            __threadfence();
        }
    }
    __syncthreads();
}

// Exclusive scan of NCELLS ints by one NT-thread block (2-pass, 36/thread).
__device__ __forceinline__ void scanN(const int* __restrict__ cnt,
                                      int* __restrict__ outp,
                                      int* __restrict__ outp2,
                                      bool write_total) {
    __shared__ int wsum[NWPB];
    int t = threadIdx.x, lane = t & 31, w = t >> 5;
    const int4* c4 = (const int4*)cnt;
    const int PT = NCELLS / NT / 4;      // int4s per thread = 9
    int tot = 0;
#pragma unroll
    for (int j = 0; j < PT; j++) {
        int4 a = c4[t * PT + j];
        tot += a.x + a.y + a.z + a.w;
    }
    int x = tot;
#pragma unroll
    for (int o = 1; o < 32; o <<= 1) {
        int u = __shfl_up_sync(0xFFFFFFFFu, x, o);
        if (lane >= o) x += u;
    }
    if (lane == 31) wsum[w] = x;
    __syncthreads();
    if (w == 0) {
        int y = wsum[lane];
#pragma unroll
        for (int o = 1; o < 32; o <<= 1) {
            int u = __shfl_up_sync(0xFFFFFFFFu, y, o);
            if (lane >= o) y += u;
        }
        wsum[lane] = y;
    }
    __syncthreads();
    int run = x - tot + (w > 0 ? wsum[w - 1] : 0);
#pragma unroll
    for (int j = 0; j < PT; j++) {
        int4 a = c4[t * PT + j];
        int4 o;
        o.x = run; o.y = run + a.x; o.z = o.y + a.y; o.w = o.z + a.z;
        run = o.w + a.w;
        ((int4*)outp)[t * PT + j] = o;
        ((int4*)outp2)[t * PT + j] = o;
    }
    if (write_total && t == NT - 1) outp[NCELLS] = run;
}

// Warp-collective count of points in clamped square radius r around (cx,cy).
__device__ __forceinline__ int count_square(int qcx, int qcy, int r, int lane) {
    int xl = max(0, qcx - r), xr = min(GS - 1, qcx + r);
    int yl = max(0, qcy - r), yh = min(GS - 1, qcy + r);
    int c = 0;
    for (int y = yl + lane; y <= yh; y += 32)
        c += g_start[y * GS + xr + 1] - g_start[y * GS + xl];
    return __reduce_add_sync(0xFFFFFFFFu, c);
}

// ---------------- the single persistent kernel ------------------------------

__global__ void __launch_bounds__(NT, 1) k_all(const float* __restrict__ ch1,
                                               const float* __restrict__ ch2,
                                               const float* __restrict__ M1,
                                               const float* __restrict__ M2,
                                               float* __restrict__ out) {
    extern __shared__ u64 s_keys[];     // interleaved: [(w*KNN + s)*32 + lane]
    __shared__ float s_red[4 * NWPB];
    __shared__ float s_sum[NWPB];

    int b = blockIdx.x, t = threadIdx.x;
    int lane = t & 31, w = t >> 5;
    int g = b * NT + t;
    int s0 = (int)(((long long)b * NPTS) / NB);
    int e0 = (int)(((long long)(b + 1) * NPTS) / NB);

    // ===== Phase A: zero counts, reset scalars, poly map + bbox =============
    {
        const int NQ4 = NCELLS / 4;      // 9216
        if (g < NQ4) ((int4*)g_counts)[g] = make_int4(0, 0, 0, 0);
        else if (g < 2 * NQ4) ((int4*)g_qcounts)[g - NQ4] = make_int4(0, 0, 0, 0);
        if (g == 0) { g_accum = 0; g_qnext = 0; }

        float m10 = M1[0], m11 = M1[1], m12 = M1[2], m13 = M1[3];
        float m20 = M2[0], m21 = M2[1], m22 = M2[2], m23 = M2[3];
        float mnx = FLT_MAX, mxx = -FLT_MAX, mny = FLT_MAX, mxy = -FLT_MAX;
        for (int i = s0 + t; i < e0; i += NT) {
            float2 c = ((const float2*)ch2)[i];
            float y1 = m10 + m11 * c.y + m12 * c.x + m13 * c.x * c.y;
            float y2 = m20 + m21 * c.y + m22 * c.x + m23 * c.x * c.y;
            g_mx[i] = y1; g_my[i] = y2;
            mnx = fminf(mnx, y1); mxx = fmaxf(mxx, y1);
            mny = fminf(mny, y2); mxy = fmaxf(mxy, y2);
        }
#pragma unroll
        for (int o = 16; o > 0; o >>= 1) {
            mnx = fminf(mnx, __shfl_xor_sync(0xFFFFFFFFu, mnx, o));
            mxx = fmaxf(mxx, __shfl_xor_sync(0xFFFFFFFFu, mxx, o));
            mny = fminf(mny, __shfl_xor_sync(0xFFFFFFFFu, mny, o));
            mxy = fmaxf(mxy, __shfl_xor_sync(0xFFFFFFFFu, mxy, o));
        }
        if (lane == 0) {
            s_red[w] = mnx; s_red[NWPB + w] = mxx;
            s_red[2 * NWPB + w] = mny; s_red[3 * NWPB + w] = mxy;
        }
        __syncthreads();
        if (w == 0) {
            float A = s_red[lane];
            float B = s_red[NWPB + lane];
            float C = s_red[2 * NWPB + lane];
            float D = s_red[3 * NWPB + lane];
#pragma unroll
            for (int o = 16; o > 0; o >>= 1) {
                A = fminf(A, __shfl_xor_sync(0xFFFFFFFFu, A, o));
                B = fmaxf(B, __shfl_xor_sync(0xFFFFFFFFu, B, o));
                C = fminf(C, __shfl_xor_sync(0xFFFFFFFFu, C, o));
                D = fmaxf(D, __shfl_xor_sync(0xFFFFFFFFu, D, o));
            }
            if (lane == 0) {
                atomicMin(&g_benc[0], encf(A));
                atomicMax(&g_benc[1], encf(B));
                atomicMin(&g_benc[2], encf(C));
                atomicMax(&g_benc[3], encf(D));
            }
        }
    }
    gbar();

    // ===== Phase B: bin points + queries ====================================
    float minx = decf(g_benc[0]), maxx = decf(g_benc[1]);
    float miny = decf(g_benc[2]), maxy = decf(g_benc[3]);
    float rxr = fmaxf(maxx - minx, 1e-20f);
    float ryr = fmaxf(maxy - miny, 1e-20f);
    float ivx = (float)GS / rxr, ivy = (float)GS / ryr;
    float hx = rxr / (float)GS, hy = ryr / (float)GS;

    for (int i = s0 + t; i < e0; i += NT) {
        int cx = min(GS - 1, max(0, (int)((g_mx[i] - minx) * ivx)));
        int cy = min(GS - 1, max(0, (int)((g_my[i] - miny) * ivy)));
        int c = cy * GS + cx;
        g_cellof[i] = c;
        atomicAdd(&g_counts[c], 1);
        float2 q = ((const float2*)ch1)[i];
        int qcx = min(GS - 1, max(0, (int)((q.x - minx) * ivx)));
        int qcy = min(GS - 1, max(0, (int)((q.y - miny) * ivy)));
        int qc = qcy * GS + qcx;
        g_qcell[i] = qc;
        atomicAdd(&g_qcounts[qc], 1);
    }
    gbar();

    // ===== Phase C: scans (blocks 0 and 1 in parallel) ======================
    if (b == 0) scanN(g_counts, g_start, g_fill, true);
    else if (b == 1) scanN(g_qcounts, g_qfill, g_qfill, false);
    gbar();

    // ===== Phase D: scatter + per-cell r0 precompute ========================
    for (int i = s0 + t; i < e0; i += NT) {
        int c = g_cellof[i];
        int p = atomicAdd(&g_fill[c], 1);
        g_bpt[p] = make_float4(g_mx[i], g_my[i], __int_as_float(i), 0.0f);
        int qc = g_qcell[i];
        int pq = atomicAdd(&g_qfill[qc], 1);
        g_qxy[pq] = ((const float2*)ch1)[i];
        g_qid[pq] = i;
    }
    // E0: exact minimal r0 per occupied query cell, lanes 0-15 test r=1..16
    {
        int wg = b * NWPB + w;
        for (int cell = wg; cell < NCELLS; cell += NWARPS) {
            if (g_qcounts[cell] == 0) continue;
            int qcx = cell % GS, qcy = cell / GS;
            int cnt = 0;
            if (lane < 16) {
                int rr = lane + 1;
                int xl = max(0, qcx - rr), xr = min(GS - 1, qcx + rr);
                int yl = max(0, qcy - rr), yh = min(GS - 1, qcy + rr);
                for (int y = yl; y <= yh; ++y)
                    cnt += g_start[y * GS + xr + 1] - g_start[y * GS + xl];
            }
            unsigned ball = __ballot_sync(0xFFFFFFFFu, (lane < 16) && (cnt >= KNN));
            int r0v;
            if (ball) {
                r0v = __ffs(ball);               // lane idx + 1 == radius
            } else {                             // sparse edge cell: expand
                int lo = 16, hi = 24;
                int c2 = count_square(qcx, qcy, hi, lane);
                while (c2 < KNN && hi < GS) {
                    lo = hi; hi = min(GS, hi + (hi >> 1));
                    c2 = count_square(qcx, qcy, hi, lane);
                }
                while (hi - lo > 1) {
                    int mid = (lo + hi) >> 1;
                    if (count_square(qcx, qcy, mid, lane) >= KNN) hi = mid;
                    else lo = mid;
                }
                r0v = hi;
            }
            if (lane == 0) g_r0[cell] = r0v;
        }
    }
    gbar();

    // ===== Phase E: dynamic warp-per-query exact 16-NN ======================
    {
        for (;;) {
            int q;
            if (lane == 0) q = atomicAdd(&g_qnext, 1);
            q = __shfl_sync(0xFFFFFFFFu, q, 0);
            if (q >= NPTS) break;

            float2 Q = g_qxy[q];
            float qx = Q.x, qy = Q.y;
            int orig = g_qid[q];
            int qcx = min(GS - 1, max(0, (int)((qx - minx) * ivx)));
            int qcy = min(GS - 1, max(0, (int)((qy - miny) * ivy)));
            int r0 = g_r0[qcy * GS + qcx];

            // D2 = far-corner bound of the r0-square around the cell.
            float dxf = fmaxf(qx - (minx + (float)(qcx - r0) * hx),
                              (minx + (float)(qcx + r0 + 1) * hx) - qx) + 1e-4f;
            float dyf = fmaxf(qy - (miny + (float)(qcy - r0) * hy),
                              (miny + (float)(qcy + r0 + 1) * hy) - qy) + 1e-4f;
            float D2 = dxf * dxf + dyf * dyf;
            float Dr = sqrtf(D2);

            int bx0 = max(0, (int)floorf((qx - Dr - minx) * ivx) - 1);
            int bx1 = min(GS - 1, (int)floorf((qx + Dr - minx) * ivx) + 1);
            int by0 = max(0, (int)floorf((qy - Dr - miny) * ivy) - 1);
            int by1 = min(GS - 1, (int)floorf((qy + Dr - miny) * ivy) + 1);

            u64 keys[KNN];
#pragma unroll
            for (int s = 0; s < KNN; s++) keys[s] = 0xFFFFFFFFFFFFFFFFull;

            for (int ybase = by0; ybase <= by1; ybase += 32) {
                int y = ybase + lane;
                int rs = 0, len = 0;
                if (y <= by1) {
                    rs = g_start[y * GS + bx0];
                    len = g_start[y * GS + bx1 + 1] - rs;
                }
                int pre = len;
#pragma unroll
                for (int o = 1; o < 32; o <<= 1) {
                    int u = __shfl_up_sync(0xFFFFFFFFu, pre, o);
                    if (lane >= o) pre += u;
                }
                int T = __shfl_sync(0xFFFFFFFFu, pre, 31);
                int excl = pre - len;

                for (int base = 0; base < T; base += 32) {
                    int idx = base + lane;
                    bool act = idx < T;
                    // find row j = max{j : excl_j <= idx} via shfl binary search
                    int jlo = 0;
#pragma unroll
                    for (int s = 16; s > 0; s >>= 1) {
                        int jm = jlo + s;
                        int ev = __shfl_sync(0xFFFFFFFFu, excl, min(jm, 31));
                        if (jm <= 31 && ev <= idx) jlo = jm;
                    }
                    int rrs = __shfl_sync(0xFFFFFFFFu, rs, jlo);
                    int rex = __shfl_sync(0xFFFFFFFFu, excl, jlo);
                    if (act) {
                        int tt = rrs + (idx - rex);
                        float4 p = g_bpt[tt];
                        float dx = qx - p.x;
                        float dy = qy - p.y;
                        float d = __fadd_rn(__fmul_rn(dx, dx), __fmul_rn(dy, dy));
                        if (d <= D2) {
                            u64 key = ((u64)__float_as_uint(d) << 32) |
                                      (unsigned)__float_as_int(p.z);
                            if (key < keys[KNN - 1]) {
                                keys[KNN - 1] = key;
#pragma unroll
                                for (int s = KNN - 1; s > 0; --s) {
                                    if (keys[s] < keys[s - 1]) {
                                        u64 tk = keys[s];
                                        keys[s] = keys[s - 1];
                                        keys[s - 1] = tk;
                                    }
                                }
                            }
                        }
                    }
                }
            }

            // exact sorted warp merge: interleaved smem + 2xREDUX per round
#pragma unroll
            for (int s = 0; s < KNN; s++)
                s_keys[(w * KNN + s) * 32 + lane] = keys[s];
            int head = 0;
            u64 cur = keys[0];
#pragma unroll 1
            for (int k = 0; k < KNN; k++) {
                unsigned hi = (unsigned)(cur >> 32);
                unsigned m = __reduce_min_sync(0xFFFFFFFFu, hi);
                unsigned lov = (hi == m) ? (unsigned)cur : 0xFFFFFFFFu;
                unsigned ml = __reduce_min_sync(0xFFFFFFFFu, lov);
                if (lane == 0) g_knn[orig * KNN + k] = (int)ml;
                if (hi == m && (unsigned)cur == ml) {
                    head++;
                    cur = (head < KNN) ? s_keys[(w * KNN + head) * 32 + lane]
                                       : 0xFFFFFFFFFFFFFFFFull;
                }
            }
        }
    }
    gbar();

    // ===== Phase F: scrambled gather + KL log-sum ===========================
    {
        float part = 0.0f;
        for (int n = s0 + t; n < e0; n += NT) {
            float2 qp = ((const float2*)ch1)[n];
            float qx = qp.x, qy = qp.y;
            int qq = n >> 4, col = n & 15;
            const float inv_s4 = 1.0f / 2.25f;  // 1 / sigma2^2, sigma2 = 1.5
            float acc = 0.0f;
#pragma unroll
            for (int k = 0; k < 16; k++) {
                int sel = g_knn[(k * 512 + qq) * KNN + col];
                float dx = qx - g_mx[sel];
                float dy = qy - g_my[sel];
                float D = 0.5f * (__fmul_rn(dx, dx) * inv_s4 + __fmul_rn(dy, dy) * inv_s4);
                acc += expf(-D);
            }
            float expD = acc * (1.0f / (float)NPTS);
            part += (expD != 0.0f) ? logf(expD) : 0.0f;
        }
#pragma unroll
        for (int o = 16; o > 0; o >>= 1)
            part += __shfl_xor_sync(0xFFFFFFFFu, part, o);
        if (lane == 0) s_sum[w] = part;
        __syncthreads();
        if (w == 0) {
            float v = s_sum[lane];
#pragma unroll
            for (int o = 16; o > 0; o >>= 1)
                v += __shfl_xor_sync(0xFFFFFFFFu, v, o);
            if (lane == 0) {
                long long fv = __double2ll_rn((double)v * FIXP);
                atomicAdd((unsigned long long*)&g_accum, (unsigned long long)fv);
            }
        }
    }
    gbar();

    if (b == 0 && t == 0)
        out[0] = (float)(-((double)g_accum / FIXP));
}

// ---------------- launch ----------------------------------------------------

extern "C" void kernel_launch(void* const* d_in, const int* in_sizes, int n_in,
                              void* d_out, int out_size) {
    (void)in_sizes; (void)n_in; (void)out_size;
    const float* ch1 = (const float*)d_in[0];
    const float* ch2 = (const float*)d_in[1];
    const float* M1  = (const float*)d_in[2];
    const float* M2  = (const float*)d_in[3];
    float* out = (float*)d_out;

    cudaFuncSetAttribute(k_all, cudaFuncAttributeMaxDynamicSharedMemorySize,
                         SMEM_KEYS_BYTES);
    k_all<<<NB, NT, SMEM_KEYS_BYTES>>>(ch1, ch2, M1, M2, out);
}